// round 14
// baseline (speedup 1.0000x reference)
#include <cuda_runtime.h>
#include <math.h>

// Problem constants (fixed shapes)
#define NN 20000
#define EE 320000
#define CC 64

// ---------------- scratch (device globals; no allocation allowed) ----------------
__device__ __align__(16) float g_s[NN * CC];            // up-projected scalars  s[n][c]
__device__ __align__(16) float g_v[NN * CC * 3];        // up-projected vectors  v[n][c][m]
__device__ __align__(16) float g_skip_s[NN * 2 * CC];   // skip_s[n][o]
__device__ __align__(16) float g_skip_v[NN * CC * 3];   // skip_v[n][o][m]
__device__ __align__(16) float g_agg_s[NN * 2 * CC];    // agg_s raw sums
__device__ __align__(16) float g_agg_v[NN * 3 * 2 * CC];// agg_v[n][m][c2] raw sums
__device__ __align__(16) float g_mix[EE * 256];         // per-edge MLP output
__device__ __align__(16) float g_y[EE * 4];             // per-edge sqrt(3)*vhat (w=0)

__device__ __forceinline__ float swishf(float x) { return x / (1.0f + __expf(-x)); }

__device__ __forceinline__ void red4(float* p, float a, float b, float c, float d) {
    asm volatile("red.global.add.v4.f32 [%0], {%1,%2,%3,%4};"
                 :: "l"(p), "f"(a), "f"(b), "f"(c), "f"(d) : "memory");
}

// ---- packed f32x2 helpers (Blackwell FFMA2 path) ----
__device__ __forceinline__ unsigned long long dup2(float a) {
    unsigned long long r;
    asm("mov.b64 %0, {%1,%1};" : "=l"(r) : "f"(a));
    return r;
}
__device__ __forceinline__ unsigned long long ffma2(unsigned long long a,
                                                    unsigned long long b,
                                                    unsigned long long c) {
    unsigned long long d;
    asm("fma.rn.f32x2 %0, %1, %2, %3;" : "=l"(d) : "l"(a), "l"(b), "l"(c));
    return d;
}
__device__ __forceinline__ float2 unpack2(unsigned long long v) {
    float2 f;
    asm("mov.b64 {%0,%1}, %2;" : "=f"(f.x), "=f"(f.y) : "l"(v));
    return f;
}

// ---------------- kernel: node up-projection + fused agg zeroing ----------------
__global__ void __launch_bounds__(256) k_up(const float* __restrict__ scal,
                                            const float* __restrict__ nvec,
                                            const float* __restrict__ Wus,
                                            const float* __restrict__ Wuv) {
    extern __shared__ float sm[];
    float* sWs = sm;          // 64*64
    float* sWv = sm + 4096;   // 64*64
    float* sBuf = sm + 8192;  // 8 warps * 256
    int tid = threadIdx.x, wid = tid >> 5, l = tid & 31;

    // fused zero of aggregation buffers (independent of this kernel's outputs;
    // k_scatter launches after k_up completes, so ordering is safe)
    {
        float4 z = make_float4(0.f, 0.f, 0.f, 0.f);
        int gtid = blockIdx.x * blockDim.x + tid;
        int gstr = gridDim.x * blockDim.x;
        int n1 = NN * 2 * CC / 4;
        for (int i = gtid; i < n1; i += gstr)
            reinterpret_cast<float4*>(g_agg_s)[i] = z;
        int n2 = NN * 6 * CC / 4;
        for (int i = gtid; i < n2; i += gstr)
            reinterpret_cast<float4*>(g_agg_v)[i] = z;
    }

    for (int i = tid; i < 4096; i += 256) { sWs[i] = Wus[i]; sWv[i] = Wuv[i]; }
    __syncthreads();
    float* sc = sBuf + wid * 256;
    float* vb = sc + 64;
    int nwarp = gridDim.x * 8;
    for (int n = blockIdx.x * 8 + wid; n < NN; n += nwarp) {
        sc[l] = scal[n * 64 + l];
        sc[l + 32] = scal[n * 64 + l + 32];
#pragma unroll
        for (int q = 0; q < 6; q++) vb[l + q * 32] = nvec[n * 192 + l + q * 32];
        __syncwarp();
        float a0 = 0.f, a1 = 0.f;
#pragma unroll
        for (int k = 0; k < 64; k++) {
            float a = sc[k];
            a0 = fmaf(a, sWs[k * 64 + l], a0);
            a1 = fmaf(a, sWs[k * 64 + l + 32], a1);
        }
        g_s[n * 64 + l] = a0;
        g_s[n * 64 + l + 32] = a1;
        float v0[3] = {0.f, 0.f, 0.f}, v1[3] = {0.f, 0.f, 0.f};
#pragma unroll
        for (int k = 0; k < 64; k++) {
            float w0 = sWv[k * 64 + l], w1 = sWv[k * 64 + l + 32];
#pragma unroll
            for (int m = 0; m < 3; m++) {
                float a = vb[k * 3 + m];
                v0[m] = fmaf(a, w0, v0[m]);
                v1[m] = fmaf(a, w1, v1[m]);
            }
        }
#pragma unroll
        for (int m = 0; m < 3; m++) {
            g_v[n * 192 + l * 3 + m] = v0[m];
            g_v[n * 192 + (l + 32) * 3 + m] = v1[m];
        }
        __syncwarp();
    }
}

// ---------------- kernel: per-species skip projections (grid 148: ONE wave) ----------------
__global__ void __launch_bounds__(256) k_skip(const float* __restrict__ scal,
                                              const float* __restrict__ nvec,
                                              const int* __restrict__ specie,
                                              const float* __restrict__ Wss,
                                              const float* __restrict__ Wsv) {
    extern __shared__ float sm[];
    float* sS = sm;            // 32768
    float* sV = sm + 32768;    // 16384
    float* sBuf = sm + 49152;  // 8 * 256
    int tid = threadIdx.x, wid = tid >> 5, l = tid & 31;
    for (int i = tid; i < 32768; i += 256) sS[i] = Wss[i];
    for (int i = tid; i < 16384; i += 256) sV[i] = Wsv[i];
    __syncthreads();
    float* sc = sBuf + wid * 256;
    float* vb = sc + 64;
    int nwarp = gridDim.x * 8;
    for (int n = blockIdx.x * 8 + wid; n < NN; n += nwarp) {
        sc[l] = scal[n * 64 + l];
        sc[l + 32] = scal[n * 64 + l + 32];
#pragma unroll
        for (int q = 0; q < 6; q++) vb[l + q * 32] = nvec[n * 192 + l + q * 32];
        __syncwarp();
        int sp = specie[n];
        const float* ws = sS + sp * 8192;
        const float* wv = sV + sp * 4096;
        float a0 = 0.f, a1 = 0.f, a2 = 0.f, a3 = 0.f;
#pragma unroll
        for (int k = 0; k < 64; k++) {
            float x = sc[k];
            const float* w = ws + k * 128;
            a0 = fmaf(x, w[l], a0);
            a1 = fmaf(x, w[l + 32], a1);
            a2 = fmaf(x, w[l + 64], a2);
            a3 = fmaf(x, w[l + 96], a3);
        }
        g_skip_s[n * 128 + l] = a0;
        g_skip_s[n * 128 + l + 32] = a1;
        g_skip_s[n * 128 + l + 64] = a2;
        g_skip_s[n * 128 + l + 96] = a3;
        float v0[3] = {0.f, 0.f, 0.f}, v1[3] = {0.f, 0.f, 0.f};
#pragma unroll
        for (int k = 0; k < 64; k++) {
            float w0 = wv[k * 64 + l], w1 = wv[k * 64 + l + 32];
#pragma unroll
            for (int m = 0; m < 3; m++) {
                float a = vb[k * 3 + m];
                v0[m] = fmaf(a, w0, v0[m]);
                v1[m] = fmaf(a, w1, v1[m]);
            }
        }
#pragma unroll
        for (int m = 0; m < 3; m++) {
            g_skip_v[n * 192 + l * 3 + m] = v0[m];
            g_skip_v[n * 192 + (l + 32) * 3 + m] = v1[m];
        }
        __syncwarp();
    }
}

// ---------------- kernel: edge MLP -> g_mix, g_y (unchanged from R13) ----------------
__global__ void __launch_bounds__(256, 2) k_mlp(const float* __restrict__ vectors,
                                                const float* __restrict__ W0,
                                                const float* __restrict__ W1,
                                                const float* __restrict__ W2) {
    extern __shared__ float sm[];
    float* sW0 = sm;                 // 512
    float* sW1 = sm + 512;           // 4096
    float* sW2 = sm + 4608;          // 16384
    float* sH  = sm + 20992;         // 64*65 = 4160, reused H0->H1
    float* sF  = sm + 25152;         // 64*9  = 576  -> total 25728 floats

    int tid = threadIdx.x;
    for (int i = tid; i < 512; i += 256) sW0[i] = W0[i];
    for (int i = tid; i < 4096; i += 256) sW1[i] = W1[i];
    for (int i = tid; i < 16384; i += 256) sW2[i] = W2[i];
    __syncthreads();

    const int og = tid >> 3;  // 0..31
    const int eg = tid & 7;   // 0..7
    const float SQRT2 = 1.41421356237309515f;
    const float SQRT3 = 1.73205080756887729f;
    const float PI = 3.14159265358979323846f;

    int ntile = EE / 64;
    for (int t = blockIdx.x; t < ntile; t += gridDim.x) {
        int e0 = t * 64;
        // ---- phase 1: per-edge features (threads 0..63) ----
        if (tid < 64) {
            int e = e0 + tid;
            float vx = vectors[e * 3 + 0];
            float vy = vectors[e * 3 + 1];
            float vz = vectors[e * 3 + 2];
            float x = sqrtf(vx * vx + vy * vy + vz * vz);
            float sx = (x == 0.f) ? 1.f : x;
            float inv = 1.f / sx;
            float4 yv = make_float4(SQRT3 * vx * inv, SQRT3 * vy * inv, SQRT3 * vz * inv, 0.f);
            *reinterpret_cast<float4*>(g_y + e * 4) = yv;
            float u = fminf(x, 1.f);
            float u2 = u * u, u3 = u2 * u, u6 = u3 * u3, u7 = u6 * u, u8 = u7 * u;
            float env = (x < 1.f) ? (1.f - 28.f * u6 + 48.f * u7 - 21.f * u8) : 0.f;
            float s1, c1;
            sincosf(PI * x, &s1, &c1);
            float pref = SQRT2 * inv * env;
            float sn = s1, cn = c1;
            sF[tid * 9 + 0] = pref * sn;
#pragma unroll
            for (int b = 1; b < 8; b++) {
                float sn1 = sn * c1 + cn * s1;
                float cn1 = cn * c1 - sn * s1;
                sn = sn1; cn = cn1;
                sF[tid * 9 + b] = pref * sn;
            }
        }
        __syncthreads();

        // ---- phase 2: h0 = swish(feat @ W0) (scalar, small) ----
        {
            float a0[8], a1[8];
#pragma unroll
            for (int i = 0; i < 8; i++) { a0[i] = 0.f; a1[i] = 0.f; }
#pragma unroll
            for (int b = 0; b < 8; b++) {
                float w0 = sW0[b * 64 + og];
                float w1 = sW0[b * 64 + og + 32];
#pragma unroll
                for (int i = 0; i < 8; i++) {
                    float f = sF[(eg + 8 * i) * 9 + b];
                    a0[i] = fmaf(f, w0, a0[i]);
                    a1[i] = fmaf(f, w1, a1[i]);
                }
            }
#pragma unroll
            for (int i = 0; i < 8; i++) {
                sH[(eg + 8 * i) * 65 + og] = swishf(a0[i]);
                sH[(eg + 8 * i) * 65 + og + 32] = swishf(a1[i]);
            }
        }
        __syncthreads();

        // ---- phase 3: h1 = swish(h0 @ W1), FFMA2 over output pair (2og, 2og+1) ----
        {
            unsigned long long acc[8];
#pragma unroll
            for (int i = 0; i < 8; i++) acc[i] = 0ULL;
            const unsigned long long* w1p =
                reinterpret_cast<const unsigned long long*>(sW1 + 2 * og);
#pragma unroll 2
            for (int k = 0; k < 64; k++) {
                unsigned long long wp = w1p[k * 32];  // (W1[k][2og], W1[k][2og+1])
#pragma unroll
                for (int i = 0; i < 8; i++) {
                    unsigned long long ad = dup2(sH[(eg + 8 * i) * 65 + k]);
                    acc[i] = ffma2(ad, wp, acc[i]);
                }
            }
            __syncthreads();  // everyone done READING h0 before in-place overwrite
#pragma unroll
            for (int i = 0; i < 8; i++) {
                float2 f = unpack2(acc[i]);
                sH[(eg + 8 * i) * 65 + 2 * og] = swishf(f.x);
                sH[(eg + 8 * i) * 65 + 2 * og + 1] = swishf(f.y);
            }
        }
        __syncthreads();

        // ---- phase 4: mix = h1 @ W2, FFMA2, thread tile 8e x 4 j-pairs ----
        unsigned long long acc[8][4];
#pragma unroll
        for (int i = 0; i < 8; i++)
#pragma unroll
            for (int q = 0; q < 4; q++) acc[i][q] = 0ULL;
        {
            const int j0 = og * 8;
#pragma unroll 2
            for (int k = 0; k < 64; k++) {
                ulonglong2 b0 = *reinterpret_cast<const ulonglong2*>(sW2 + k * 256 + j0);
                ulonglong2 b1 = *reinterpret_cast<const ulonglong2*>(sW2 + k * 256 + j0 + 4);
#pragma unroll
                for (int i = 0; i < 8; i++) {
                    unsigned long long ad = dup2(sH[(eg + 8 * i) * 65 + k]);
                    acc[i][0] = ffma2(ad, b0.x, acc[i][0]);
                    acc[i][1] = ffma2(ad, b0.y, acc[i][1]);
                    acc[i][2] = ffma2(ad, b1.x, acc[i][2]);
                    acc[i][3] = ffma2(ad, b1.y, acc[i][3]);
                }
            }
        }

        // ---- phase 5': store mix coalesced (u64 pairs = consecutive j floats) ----
        {
            const int j0 = og * 8;
#pragma unroll
            for (int i = 0; i < 8; i++) {
                int e = e0 + eg + 8 * i;
                ulonglong2 lo, hi;
                lo.x = acc[i][0]; lo.y = acc[i][1];
                hi.x = acc[i][2]; hi.y = acc[i][3];
                *reinterpret_cast<ulonglong2*>(g_mix + e * 256 + j0) = lo;
                *reinterpret_cast<ulonglong2*>(g_mix + e * 256 + j0 + 4) = hi;
            }
        }
        __syncthreads();
    }
}

// ---------------- kernel: gather + message + scatter (warp-per-edge, unchanged) ----------------
__global__ void __launch_bounds__(256) k_scatter(const int* __restrict__ senders,
                                                 const int* __restrict__ receivers) {
    __shared__ float sb[8][520];  // per warp: S[64] V[192] M[256] Y[4] (+pad)
    int tid = threadIdx.x;
    int w = tid >> 5, l = tid & 31;
    const float INV_SQRT3 = 0.57735026918962576f;
    float* S = sb[w];
    float* V = S + 64;
    float* M = V + 192;
    float* Yp = M + 256;
    int nwarp = gridDim.x * 8;
    for (int e = blockIdx.x * 8 + w; e < EE; e += nwarp) {
        int snd = senders[e];
        int rcv = receivers[e];
        *reinterpret_cast<float4*>(M + l * 4) =
            *reinterpret_cast<const float4*>(g_mix + e * 256 + l * 4);
        *reinterpret_cast<float4*>(M + (l + 32) * 4) =
            *reinterpret_cast<const float4*>(g_mix + e * 256 + (l + 32) * 4);
        *reinterpret_cast<float4*>(V + l * 4) =
            *reinterpret_cast<const float4*>(g_v + snd * 192 + l * 4);
        if (l < 16)
            *reinterpret_cast<float4*>(V + (l + 32) * 4) =
                *reinterpret_cast<const float4*>(g_v + snd * 192 + (l + 32) * 4);
        if (l < 16)
            *reinterpret_cast<float4*>(S + l * 4) =
                *reinterpret_cast<const float4*>(g_s + snd * 64 + l * 4);
        if (l == 0)
            *reinterpret_cast<float4*>(Yp) = *reinterpret_cast<const float4*>(g_y + e * 4);
        __syncwarp();

#pragma unroll
        for (int j = 0; j < 4; j++) {
            int o = l + 32 * j;  // 0..127
            if (o < 16) {
                int c = o * 4;
                red4(g_agg_s + rcv * 128 + c,
                     S[c] * M[c], S[c + 1] * M[c + 1],
                     S[c + 2] * M[c + 2], S[c + 3] * M[c + 3]);
            } else if (o < 32) {
                int c = (o - 16) * 4;
                float y0 = Yp[0], y1 = Yp[1], y2 = Yp[2];
                float v[4];
#pragma unroll
                for (int t = 0; t < 4; t++) {
                    int cc = c + t;
                    v[t] = (V[cc * 3] * y0 + V[cc * 3 + 1] * y1 + V[cc * 3 + 2] * y2)
                           * INV_SQRT3 * M[64 + cc];
                }
                red4(g_agg_s + rcv * 128 + 64 + c, v[0], v[1], v[2], v[3]);
            } else {
                int q = o - 32;          // 0..95
                int m = q >> 5, cb = q & 31;
                int c2 = cb * 4;
                float v[4];
                if (c2 < 64) {
#pragma unroll
                    for (int t = 0; t < 4; t++)
                        v[t] = V[(c2 + t) * 3 + m] * M[128 + c2 + t];
                } else {
                    int c = c2 - 64;
                    float ym = Yp[m];
#pragma unroll
                    for (int t = 0; t < 4; t++)
                        v[t] = S[c + t] * ym * M[192 + c + t];
                }
                red4(g_agg_v + rcv * 384 + m * 128 + c2, v[0], v[1], v[2], v[3]);
            }
        }
        __syncwarp();
    }
}

// ---------------- kernel: final down-projection + skip + gating + output ----------------
// grid 148: one wave at 1 block/SM, weights staged once per SM.
__global__ void __launch_bounds__(256) k_final(const float* __restrict__ Wds,
                                               const float* __restrict__ Wdv,
                                               float* __restrict__ out) {
    extern __shared__ float sm[];
    float* sWs = sm;            // 16384
    float* sWv = sm + 16384;    // 8192
    float* sBuf = sm + 24576;   // 8 * 520
    int tid = threadIdx.x, wid = tid >> 5, l = tid & 31;
    for (int i = tid; i < 16384; i += 256) sWs[i] = Wds[i];
    for (int i = tid; i < 8192; i += 256) sWv[i] = Wdv[i];
    __syncthreads();
    float* As = sBuf + wid * 520;
    float* Av = As + 128;
    const float INV = 0.25f;
    int nwarp = gridDim.x * 8;
    for (int n = blockIdx.x * 8 + wid; n < NN; n += nwarp) {
#pragma unroll
        for (int q = 0; q < 4; q++) As[l + 32 * q] = g_agg_s[n * 128 + l + 32 * q];
#pragma unroll
        for (int q = 0; q < 12; q++) Av[l + 32 * q] = g_agg_v[n * 384 + l + 32 * q];
        __syncwarp();
        float a0 = 0.f, a1 = 0.f, a2 = 0.f, a3 = 0.f;
#pragma unroll 4
        for (int k = 0; k < 128; k++) {
            float x = As[k];
            const float* w = sWs + k * 128;
            a0 = fmaf(x, w[l], a0);
            a1 = fmaf(x, w[l + 32], a1);
            a2 = fmaf(x, w[l + 64], a2);
            a3 = fmaf(x, w[l + 96], a3);
        }
        float os0 = INV * a0 + g_skip_s[n * 128 + l];
        float os1 = INV * a1 + g_skip_s[n * 128 + l + 32];
        float os2 = INV * a2 + g_skip_s[n * 128 + l + 64];
        float os3 = INV * a3 + g_skip_s[n * 128 + l + 96];
        float scal0 = swishf(os0), scal1 = swishf(os1);
        float gate0 = swishf(os2), gate1 = swishf(os3);
        float v0[3] = {0.f, 0.f, 0.f}, v1[3] = {0.f, 0.f, 0.f};
#pragma unroll 4
        for (int k = 0; k < 128; k++) {
            float w0 = sWv[k * 64 + l], w1 = sWv[k * 64 + l + 32];
#pragma unroll
            for (int m = 0; m < 3; m++) {
                float a = Av[m * 128 + k];
                v0[m] = fmaf(a, w0, v0[m]);
                v1[m] = fmaf(a, w1, v1[m]);
            }
        }
        out[n * 256 + l] = scal0;
        out[n * 256 + l + 32] = scal1;
#pragma unroll
        for (int m = 0; m < 3; m++) {
            float ov0 = INV * v0[m] + g_skip_v[n * 192 + l * 3 + m];
            float ov1 = INV * v1[m] + g_skip_v[n * 192 + (l + 32) * 3 + m];
            out[n * 256 + 64 + l * 3 + m] = ov0 * gate0;
            out[n * 256 + 64 + (l + 32) * 3 + m] = ov1 * gate1;
        }
        __syncwarp();
    }
}

// ---------------- launch ----------------
extern "C" void kernel_launch(void* const* d_in, const int* in_sizes, int n_in,
                              void* d_out, int out_size) {
    const float* vectors      = (const float*)d_in[0];
    const float* node_scalars = (const float*)d_in[1];
    const float* node_vectors = (const float*)d_in[2];
    const int*   node_specie  = (const int*)d_in[3];
    const int*   senders      = (const int*)d_in[4];
    const int*   receivers    = (const int*)d_in[5];
    const float* W_skip_s     = (const float*)d_in[6];
    const float* W_skip_v     = (const float*)d_in[7];
    const float* W_up_s       = (const float*)d_in[8];
    const float* W_up_v       = (const float*)d_in[9];
    const float* W_mlp0       = (const float*)d_in[10];
    const float* W_mlp1       = (const float*)d_in[11];
    const float* W_mlp2       = (const float*)d_in[12];
    const float* W_down_s     = (const float*)d_in[13];
    const float* W_down_v     = (const float*)d_in[14];
    float* out = (float*)d_out;

    const int UP_SMEM    = (8192 + 8 * 256) * 4;            // 40 KB
    const int SKIP_SMEM  = (49152 + 8 * 256) * 4;           // 200 KB
    const int MLP_SMEM   = 25728 * 4;                       // ~100.5 KB -> 2 blocks/SM
    const int FINAL_SMEM = (24576 + 8 * 520) * 4;           // ~114.5 KB -> 1 block/SM

    cudaFuncSetAttribute(k_skip,  cudaFuncAttributeMaxDynamicSharedMemorySize, SKIP_SMEM);
    cudaFuncSetAttribute(k_mlp,   cudaFuncAttributeMaxDynamicSharedMemorySize, MLP_SMEM);
    cudaFuncSetAttribute(k_final, cudaFuncAttributeMaxDynamicSharedMemorySize, FINAL_SMEM);

    k_up<<<296, 256, UP_SMEM>>>(node_scalars, node_vectors, W_up_s, W_up_v);
    k_skip<<<148, 256, SKIP_SMEM>>>(node_scalars, node_vectors, node_specie, W_skip_s, W_skip_v);
    k_mlp<<<296, 256, MLP_SMEM>>>(vectors, W_mlp0, W_mlp1, W_mlp2);
    k_scatter<<<2960, 256>>>(senders, receivers);
    k_final<<<148, 256, FINAL_SMEM>>>(W_down_s, W_down_v, out);
}

// round 15
// speedup vs baseline: 1.0898x; 1.0898x over previous
#include <cuda_runtime.h>
#include <cuda_fp16.h>
#include <math.h>

// Problem constants (fixed shapes)
#define NN 20000
#define EE 320000
#define CC 64

// ---------------- scratch (device globals; no allocation allowed) ----------------
__device__ __align__(16) float g_s[NN * CC];            // up-projected scalars  s[n][c]
__device__ __align__(16) float g_v[NN * CC * 3];        // up-projected vectors  v[n][c][m]
__device__ __align__(16) float g_skip_s[NN * 2 * CC];   // skip_s[n][o]
__device__ __align__(16) float g_skip_v[NN * CC * 3];   // skip_v[n][o][m]
__device__ __align__(16) float g_agg_s[NN * 2 * CC];    // agg_s raw sums
__device__ __align__(16) float g_agg_v[NN * 3 * 2 * CC];// agg_v[n][m][c2] raw sums
__device__ __align__(16) __half g_mix[EE * 256];        // per-edge MLP output (fp16)
__device__ __align__(16) float g_y[EE * 4];             // per-edge sqrt(3)*vhat (w=0)

__device__ __forceinline__ float swishf(float x) { return x / (1.0f + __expf(-x)); }

__device__ __forceinline__ void red4(float* p, float a, float b, float c, float d) {
    asm volatile("red.global.add.v4.f32 [%0], {%1,%2,%3,%4};"
                 :: "l"(p), "f"(a), "f"(b), "f"(c), "f"(d) : "memory");
}

// ---- packed f32x2 helpers (Blackwell FFMA2 path) ----
__device__ __forceinline__ unsigned long long dup2(float a) {
    unsigned long long r;
    asm("mov.b64 %0, {%1,%1};" : "=l"(r) : "f"(a));
    return r;
}
__device__ __forceinline__ unsigned long long ffma2(unsigned long long a,
                                                    unsigned long long b,
                                                    unsigned long long c) {
    unsigned long long d;
    asm("fma.rn.f32x2 %0, %1, %2, %3;" : "=l"(d) : "l"(a), "l"(b), "l"(c));
    return d;
}
__device__ __forceinline__ float2 unpack2(unsigned long long v) {
    float2 f;
    asm("mov.b64 {%0,%1}, %2;" : "=f"(f.x), "=f"(f.y) : "l"(v));
    return f;
}

// ---------------- kernel: zero aggregation buffers ----------------
__global__ void k_zero() {
    float4 z = make_float4(0.f, 0.f, 0.f, 0.f);
    int n1 = NN * 2 * CC / 4;
    for (int i = blockIdx.x * blockDim.x + threadIdx.x; i < n1; i += gridDim.x * blockDim.x)
        reinterpret_cast<float4*>(g_agg_s)[i] = z;
    int n2 = NN * 6 * CC / 4;
    for (int i = blockIdx.x * blockDim.x + threadIdx.x; i < n2; i += gridDim.x * blockDim.x)
        reinterpret_cast<float4*>(g_agg_v)[i] = z;
}

// ---------------- kernel: node up-projection ----------------
__global__ void __launch_bounds__(256) k_up(const float* __restrict__ scal,
                                            const float* __restrict__ nvec,
                                            const float* __restrict__ Wus,
                                            const float* __restrict__ Wuv) {
    extern __shared__ float sm[];
    float* sWs = sm;          // 64*64
    float* sWv = sm + 4096;   // 64*64
    float* sBuf = sm + 8192;  // 8 warps * 256
    int tid = threadIdx.x, wid = tid >> 5, l = tid & 31;
    for (int i = tid; i < 4096; i += 256) { sWs[i] = Wus[i]; sWv[i] = Wuv[i]; }
    __syncthreads();
    float* sc = sBuf + wid * 256;
    float* vb = sc + 64;
    int nwarp = gridDim.x * 8;
    for (int n = blockIdx.x * 8 + wid; n < NN; n += nwarp) {
        sc[l] = scal[n * 64 + l];
        sc[l + 32] = scal[n * 64 + l + 32];
#pragma unroll
        for (int q = 0; q < 6; q++) vb[l + q * 32] = nvec[n * 192 + l + q * 32];
        __syncwarp();
        float a0 = 0.f, a1 = 0.f;
#pragma unroll
        for (int k = 0; k < 64; k++) {
            float a = sc[k];
            a0 = fmaf(a, sWs[k * 64 + l], a0);
            a1 = fmaf(a, sWs[k * 64 + l + 32], a1);
        }
        g_s[n * 64 + l] = a0;
        g_s[n * 64 + l + 32] = a1;
        float v0[3] = {0.f, 0.f, 0.f}, v1[3] = {0.f, 0.f, 0.f};
#pragma unroll
        for (int k = 0; k < 64; k++) {
            float w0 = sWv[k * 64 + l], w1 = sWv[k * 64 + l + 32];
#pragma unroll
            for (int m = 0; m < 3; m++) {
                float a = vb[k * 3 + m];
                v0[m] = fmaf(a, w0, v0[m]);
                v1[m] = fmaf(a, w1, v1[m]);
            }
        }
#pragma unroll
        for (int m = 0; m < 3; m++) {
            g_v[n * 192 + l * 3 + m] = v0[m];
            g_v[n * 192 + (l + 32) * 3 + m] = v1[m];
        }
        __syncwarp();
    }
}

// ---------------- kernel: per-species skip projections ----------------
__global__ void __launch_bounds__(256) k_skip(const float* __restrict__ scal,
                                              const float* __restrict__ nvec,
                                              const int* __restrict__ specie,
                                              const float* __restrict__ Wss,
                                              const float* __restrict__ Wsv) {
    extern __shared__ float sm[];
    float* sS = sm;            // 32768
    float* sV = sm + 32768;    // 16384
    float* sBuf = sm + 49152;  // 8 * 256
    int tid = threadIdx.x, wid = tid >> 5, l = tid & 31;
    for (int i = tid; i < 32768; i += 256) sS[i] = Wss[i];
    for (int i = tid; i < 16384; i += 256) sV[i] = Wsv[i];
    __syncthreads();
    float* sc = sBuf + wid * 256;
    float* vb = sc + 64;
    int nwarp = gridDim.x * 8;
    for (int n = blockIdx.x * 8 + wid; n < NN; n += nwarp) {
        sc[l] = scal[n * 64 + l];
        sc[l + 32] = scal[n * 64 + l + 32];
#pragma unroll
        for (int q = 0; q < 6; q++) vb[l + q * 32] = nvec[n * 192 + l + q * 32];
        __syncwarp();
        int sp = specie[n];
        const float* ws = sS + sp * 8192;
        const float* wv = sV + sp * 4096;
        float a0 = 0.f, a1 = 0.f, a2 = 0.f, a3 = 0.f;
#pragma unroll
        for (int k = 0; k < 64; k++) {
            float x = sc[k];
            const float* w = ws + k * 128;
            a0 = fmaf(x, w[l], a0);
            a1 = fmaf(x, w[l + 32], a1);
            a2 = fmaf(x, w[l + 64], a2);
            a3 = fmaf(x, w[l + 96], a3);
        }
        g_skip_s[n * 128 + l] = a0;
        g_skip_s[n * 128 + l + 32] = a1;
        g_skip_s[n * 128 + l + 64] = a2;
        g_skip_s[n * 128 + l + 96] = a3;
        float v0[3] = {0.f, 0.f, 0.f}, v1[3] = {0.f, 0.f, 0.f};
#pragma unroll
        for (int k = 0; k < 64; k++) {
            float w0 = wv[k * 64 + l], w1 = wv[k * 64 + l + 32];
#pragma unroll
            for (int m = 0; m < 3; m++) {
                float a = vb[k * 3 + m];
                v0[m] = fmaf(a, w0, v0[m]);
                v1[m] = fmaf(a, w1, v1[m]);
            }
        }
#pragma unroll
        for (int m = 0; m < 3; m++) {
            g_skip_v[n * 192 + l * 3 + m] = v0[m];
            g_skip_v[n * 192 + (l + 32) * 3 + m] = v1[m];
        }
        __syncwarp();
    }
}

// ---------------- kernel: edge MLP -> g_mix (fp16), g_y ----------------
// R13 structure; only phase 5' changes: convert acc pairs to half2 and store
// 16B packets (halves the g_mix DRAM stream).
__global__ void __launch_bounds__(256, 2) k_mlp(const float* __restrict__ vectors,
                                                const float* __restrict__ W0,
                                                const float* __restrict__ W1,
                                                const float* __restrict__ W2) {
    extern __shared__ float sm[];
    float* sW0 = sm;                 // 512
    float* sW1 = sm + 512;           // 4096
    float* sW2 = sm + 4608;          // 16384
    float* sH  = sm + 20992;         // 64*65 = 4160, reused H0->H1
    float* sF  = sm + 25152;         // 64*9  = 576  -> total 25728 floats

    int tid = threadIdx.x;
    for (int i = tid; i < 512; i += 256) sW0[i] = W0[i];
    for (int i = tid; i < 4096; i += 256) sW1[i] = W1[i];
    for (int i = tid; i < 16384; i += 256) sW2[i] = W2[i];
    __syncthreads();

    const int og = tid >> 3;  // 0..31
    const int eg = tid & 7;   // 0..7
    const float SQRT2 = 1.41421356237309515f;
    const float SQRT3 = 1.73205080756887729f;
    const float PI = 3.14159265358979323846f;

    int ntile = EE / 64;
    for (int t = blockIdx.x; t < ntile; t += gridDim.x) {
        int e0 = t * 64;
        // ---- phase 1: per-edge features (threads 0..63) ----
        if (tid < 64) {
            int e = e0 + tid;
            float vx = vectors[e * 3 + 0];
            float vy = vectors[e * 3 + 1];
            float vz = vectors[e * 3 + 2];
            float x = sqrtf(vx * vx + vy * vy + vz * vz);
            float sx = (x == 0.f) ? 1.f : x;
            float inv = 1.f / sx;
            float4 yv = make_float4(SQRT3 * vx * inv, SQRT3 * vy * inv, SQRT3 * vz * inv, 0.f);
            *reinterpret_cast<float4*>(g_y + e * 4) = yv;
            float u = fminf(x, 1.f);
            float u2 = u * u, u3 = u2 * u, u6 = u3 * u3, u7 = u6 * u, u8 = u7 * u;
            float env = (x < 1.f) ? (1.f - 28.f * u6 + 48.f * u7 - 21.f * u8) : 0.f;
            float s1, c1;
            sincosf(PI * x, &s1, &c1);
            float pref = SQRT2 * inv * env;
            float sn = s1, cn = c1;
            sF[tid * 9 + 0] = pref * sn;
#pragma unroll
            for (int b = 1; b < 8; b++) {
                float sn1 = sn * c1 + cn * s1;
                float cn1 = cn * c1 - sn * s1;
                sn = sn1; cn = cn1;
                sF[tid * 9 + b] = pref * sn;
            }
        }
        __syncthreads();

        // ---- phase 2: h0 = swish(feat @ W0) ----
        {
            float a0[8], a1[8];
#pragma unroll
            for (int i = 0; i < 8; i++) { a0[i] = 0.f; a1[i] = 0.f; }
#pragma unroll
            for (int b = 0; b < 8; b++) {
                float w0 = sW0[b * 64 + og];
                float w1 = sW0[b * 64 + og + 32];
#pragma unroll
                for (int i = 0; i < 8; i++) {
                    float f = sF[(eg + 8 * i) * 9 + b];
                    a0[i] = fmaf(f, w0, a0[i]);
                    a1[i] = fmaf(f, w1, a1[i]);
                }
            }
#pragma unroll
            for (int i = 0; i < 8; i++) {
                sH[(eg + 8 * i) * 65 + og] = swishf(a0[i]);
                sH[(eg + 8 * i) * 65 + og + 32] = swishf(a1[i]);
            }
        }
        __syncthreads();

        // ---- phase 3: h1 = swish(h0 @ W1), FFMA2 over output pair (2og, 2og+1) ----
        {
            unsigned long long acc[8];
#pragma unroll
            for (int i = 0; i < 8; i++) acc[i] = 0ULL;
            const unsigned long long* w1p =
                reinterpret_cast<const unsigned long long*>(sW1 + 2 * og);
#pragma unroll 2
            for (int k = 0; k < 64; k++) {
                unsigned long long wp = w1p[k * 32];
#pragma unroll
                for (int i = 0; i < 8; i++) {
                    unsigned long long ad = dup2(sH[(eg + 8 * i) * 65 + k]);
                    acc[i] = ffma2(ad, wp, acc[i]);
                }
            }
            __syncthreads();
#pragma unroll
            for (int i = 0; i < 8; i++) {
                float2 f = unpack2(acc[i]);
                sH[(eg + 8 * i) * 65 + 2 * og] = swishf(f.x);
                sH[(eg + 8 * i) * 65 + 2 * og + 1] = swishf(f.y);
            }
        }
        __syncthreads();

        // ---- phase 4: mix = h1 @ W2, FFMA2, thread tile 8e x 4 j-pairs ----
        unsigned long long acc[8][4];
#pragma unroll
        for (int i = 0; i < 8; i++)
#pragma unroll
            for (int q = 0; q < 4; q++) acc[i][q] = 0ULL;
        {
            const int j0 = og * 8;
#pragma unroll 2
            for (int k = 0; k < 64; k++) {
                ulonglong2 b0 = *reinterpret_cast<const ulonglong2*>(sW2 + k * 256 + j0);
                ulonglong2 b1 = *reinterpret_cast<const ulonglong2*>(sW2 + k * 256 + j0 + 4);
#pragma unroll
                for (int i = 0; i < 8; i++) {
                    unsigned long long ad = dup2(sH[(eg + 8 * i) * 65 + k]);
                    acc[i][0] = ffma2(ad, b0.x, acc[i][0]);
                    acc[i][1] = ffma2(ad, b0.y, acc[i][1]);
                    acc[i][2] = ffma2(ad, b1.x, acc[i][2]);
                    acc[i][3] = ffma2(ad, b1.y, acc[i][3]);
                }
            }
        }

        // ---- phase 5': convert to fp16, store 16B packets (8 halves) ----
        {
            const int j0 = og * 8;
#pragma unroll
            for (int i = 0; i < 8; i++) {
                int e = e0 + eg + 8 * i;
                union { uint4 u; __half2 h[4]; } pk;
                pk.h[0] = __float22half2_rn(unpack2(acc[i][0]));
                pk.h[1] = __float22half2_rn(unpack2(acc[i][1]));
                pk.h[2] = __float22half2_rn(unpack2(acc[i][2]));
                pk.h[3] = __float22half2_rn(unpack2(acc[i][3]));
                *reinterpret_cast<uint4*>(g_mix + e * 256 + j0) = pk.u;
            }
        }
        __syncthreads();
    }
}

// ---------------- kernel: gather + message + scatter (warp-per-edge) ----------------
// fp16 mix: each lane loads 4 halves (8B) twice, converts, stages as float.
__global__ void __launch_bounds__(256) k_scatter(const int* __restrict__ senders,
                                                 const int* __restrict__ receivers) {
    __shared__ float sb[8][520];  // per warp: S[64] V[192] M[256] Y[4] (+pad)
    int tid = threadIdx.x;
    int w = tid >> 5, l = tid & 31;
    const float INV_SQRT3 = 0.57735026918962576f;
    float* S = sb[w];
    float* V = S + 64;
    float* M = V + 192;
    float* Yp = M + 256;
    int nwarp = gridDim.x * 8;
    for (int e = blockIdx.x * 8 + w; e < EE; e += nwarp) {
        int snd = senders[e];
        int rcv = receivers[e];
        // mix fp16: 256 halves; lane l stages floats [4l..4l+3] and [128+4l..]
#pragma unroll
        for (int half = 0; half < 2; half++) {
            int base = half * 128 + l * 4;
            union { uint2 u; __half2 h[2]; } pk;
            pk.u = *reinterpret_cast<const uint2*>(g_mix + e * 256 + base);
            float2 f0 = __half22float2(pk.h[0]);
            float2 f1 = __half22float2(pk.h[1]);
            *reinterpret_cast<float4*>(M + base) = make_float4(f0.x, f0.y, f1.x, f1.y);
        }
        *reinterpret_cast<float4*>(V + l * 4) =
            *reinterpret_cast<const float4*>(g_v + snd * 192 + l * 4);
        if (l < 16)
            *reinterpret_cast<float4*>(V + (l + 32) * 4) =
                *reinterpret_cast<const float4*>(g_v + snd * 192 + (l + 32) * 4);
        if (l < 16)
            *reinterpret_cast<float4*>(S + l * 4) =
                *reinterpret_cast<const float4*>(g_s + snd * 64 + l * 4);
        if (l == 0)
            *reinterpret_cast<float4*>(Yp) = *reinterpret_cast<const float4*>(g_y + e * 4);
        __syncwarp();

#pragma unroll
        for (int j = 0; j < 4; j++) {
            int o = l + 32 * j;  // 0..127
            if (o < 16) {
                int c = o * 4;
                red4(g_agg_s + rcv * 128 + c,
                     S[c] * M[c], S[c + 1] * M[c + 1],
                     S[c + 2] * M[c + 2], S[c + 3] * M[c + 3]);
            } else if (o < 32) {
                int c = (o - 16) * 4;
                float y0 = Yp[0], y1 = Yp[1], y2 = Yp[2];
                float v[4];
#pragma unroll
                for (int t = 0; t < 4; t++) {
                    int cc = c + t;
                    v[t] = (V[cc * 3] * y0 + V[cc * 3 + 1] * y1 + V[cc * 3 + 2] * y2)
                           * INV_SQRT3 * M[64 + cc];
                }
                red4(g_agg_s + rcv * 128 + 64 + c, v[0], v[1], v[2], v[3]);
            } else {
                int q = o - 32;          // 0..95
                int m = q >> 5, cb = q & 31;
                int c2 = cb * 4;
                float v[4];
                if (c2 < 64) {
#pragma unroll
                    for (int t = 0; t < 4; t++)
                        v[t] = V[(c2 + t) * 3 + m] * M[128 + c2 + t];
                } else {
                    int c = c2 - 64;
                    float ym = Yp[m];
#pragma unroll
                    for (int t = 0; t < 4; t++)
                        v[t] = S[c + t] * ym * M[192 + c + t];
                }
                red4(g_agg_v + rcv * 384 + m * 128 + c2, v[0], v[1], v[2], v[3]);
            }
        }
        __syncwarp();
    }
}

// ---------------- kernel: final down-projection + skip + gating + output ----------------
__global__ void __launch_bounds__(256) k_final(const float* __restrict__ Wds,
                                               const float* __restrict__ Wdv,
                                               float* __restrict__ out) {
    extern __shared__ float sm[];
    float* sWs = sm;            // 16384
    float* sWv = sm + 16384;    // 8192
    float* sBuf = sm + 24576;   // 8 * 520
    int tid = threadIdx.x, wid = tid >> 5, l = tid & 31;
    for (int i = tid; i < 16384; i += 256) sWs[i] = Wds[i];
    for (int i = tid; i < 8192; i += 256) sWv[i] = Wdv[i];
    __syncthreads();
    float* As = sBuf + wid * 520;
    float* Av = As + 128;
    const float INV = 0.25f;
    int nwarp = gridDim.x * 8;
    for (int n = blockIdx.x * 8 + wid; n < NN; n += nwarp) {
#pragma unroll
        for (int q = 0; q < 4; q++) As[l + 32 * q] = g_agg_s[n * 128 + l + 32 * q];
#pragma unroll
        for (int q = 0; q < 12; q++) Av[l + 32 * q] = g_agg_v[n * 384 + l + 32 * q];
        __syncwarp();
        float a0 = 0.f, a1 = 0.f, a2 = 0.f, a3 = 0.f;
#pragma unroll 4
        for (int k = 0; k < 128; k++) {
            float x = As[k];
            const float* w = sWs + k * 128;
            a0 = fmaf(x, w[l], a0);
            a1 = fmaf(x, w[l + 32], a1);
            a2 = fmaf(x, w[l + 64], a2);
            a3 = fmaf(x, w[l + 96], a3);
        }
        float os0 = INV * a0 + g_skip_s[n * 128 + l];
        float os1 = INV * a1 + g_skip_s[n * 128 + l + 32];
        float os2 = INV * a2 + g_skip_s[n * 128 + l + 64];
        float os3 = INV * a3 + g_skip_s[n * 128 + l + 96];
        float scal0 = swishf(os0), scal1 = swishf(os1);
        float gate0 = swishf(os2), gate1 = swishf(os3);
        float v0[3] = {0.f, 0.f, 0.f}, v1[3] = {0.f, 0.f, 0.f};
#pragma unroll 4
        for (int k = 0; k < 128; k++) {
            float w0 = sWv[k * 64 + l], w1 = sWv[k * 64 + l + 32];
#pragma unroll
            for (int m = 0; m < 3; m++) {
                float a = Av[m * 128 + k];
                v0[m] = fmaf(a, w0, v0[m]);
                v1[m] = fmaf(a, w1, v1[m]);
            }
        }
        out[n * 256 + l] = scal0;
        out[n * 256 + l + 32] = scal1;
#pragma unroll
        for (int m = 0; m < 3; m++) {
            float ov0 = INV * v0[m] + g_skip_v[n * 192 + l * 3 + m];
            float ov1 = INV * v1[m] + g_skip_v[n * 192 + (l + 32) * 3 + m];
            out[n * 256 + 64 + l * 3 + m] = ov0 * gate0;
            out[n * 256 + 64 + (l + 32) * 3 + m] = ov1 * gate1;
        }
        __syncwarp();
    }
}

// ---------------- launch (R13 configuration) ----------------
extern "C" void kernel_launch(void* const* d_in, const int* in_sizes, int n_in,
                              void* d_out, int out_size) {
    const float* vectors      = (const float*)d_in[0];
    const float* node_scalars = (const float*)d_in[1];
    const float* node_vectors = (const float*)d_in[2];
    const int*   node_specie  = (const int*)d_in[3];
    const int*   senders      = (const int*)d_in[4];
    const int*   receivers    = (const int*)d_in[5];
    const float* W_skip_s     = (const float*)d_in[6];
    const float* W_skip_v     = (const float*)d_in[7];
    const float* W_up_s       = (const float*)d_in[8];
    const float* W_up_v       = (const float*)d_in[9];
    const float* W_mlp0       = (const float*)d_in[10];
    const float* W_mlp1       = (const float*)d_in[11];
    const float* W_mlp2       = (const float*)d_in[12];
    const float* W_down_s     = (const float*)d_in[13];
    const float* W_down_v     = (const float*)d_in[14];
    float* out = (float*)d_out;

    const int UP_SMEM    = (8192 + 8 * 256) * 4;            // 40 KB
    const int SKIP_SMEM  = (49152 + 8 * 256) * 4;           // 200 KB
    const int MLP_SMEM   = 25728 * 4;                       // ~100.5 KB -> 2 blocks/SM
    const int FINAL_SMEM = (24576 + 8 * 520) * 4;           // ~114.5 KB

    cudaFuncSetAttribute(k_skip,  cudaFuncAttributeMaxDynamicSharedMemorySize, SKIP_SMEM);
    cudaFuncSetAttribute(k_mlp,   cudaFuncAttributeMaxDynamicSharedMemorySize, MLP_SMEM);
    cudaFuncSetAttribute(k_final, cudaFuncAttributeMaxDynamicSharedMemorySize, FINAL_SMEM);

    k_zero<<<2048, 256>>>();
    k_up<<<512, 256, UP_SMEM>>>(node_scalars, node_vectors, W_up_s, W_up_v);
    k_skip<<<296, 256, SKIP_SMEM>>>(node_scalars, node_vectors, node_specie, W_skip_s, W_skip_v);
    k_mlp<<<296, 256, MLP_SMEM>>>(vectors, W_mlp0, W_mlp1, W_mlp2);
    k_scatter<<<2960, 256>>>(senders, receivers);
    k_final<<<296, 256, FINAL_SMEM>>>(W_down_s, W_down_v, out);
}

// round 16
// speedup vs baseline: 1.0915x; 1.0015x over previous
#include <cuda_runtime.h>
#include <cuda_fp16.h>
#include <math.h>

// Problem constants (fixed shapes)
#define NN 20000
#define EE 320000
#define CC 64

// ---------------- scratch (device globals; no allocation allowed) ----------------
__device__ __align__(16) __half g_s[NN * CC];           // up-projected scalars (fp16)
__device__ __align__(16) __half g_v[NN * CC * 3];       // up-projected vectors (fp16)
__device__ __align__(16) float g_skip_s[NN * 2 * CC];   // skip_s[n][o]
__device__ __align__(16) float g_skip_v[NN * CC * 3];   // skip_v[n][o][m]
__device__ __align__(16) float g_agg_s[NN * 2 * CC];    // agg_s raw sums
__device__ __align__(16) float g_agg_v[NN * 3 * 2 * CC];// agg_v[n][m][c2] raw sums
__device__ __align__(16) __half g_mix[EE * 256];        // per-edge MLP output (fp16)
__device__ __align__(16) float g_y[EE * 4];             // per-edge sqrt(3)*vhat (w=0)

__device__ __forceinline__ float swishf(float x) { return x / (1.0f + __expf(-x)); }

__device__ __forceinline__ void red4(float* p, float a, float b, float c, float d) {
    asm volatile("red.global.add.v4.f32 [%0], {%1,%2,%3,%4};"
                 :: "l"(p), "f"(a), "f"(b), "f"(c), "f"(d) : "memory");
}

// ---- packed f32x2 helpers (Blackwell FFMA2 path) ----
__device__ __forceinline__ unsigned long long dup2(float a) {
    unsigned long long r;
    asm("mov.b64 %0, {%1,%1};" : "=l"(r) : "f"(a));
    return r;
}
__device__ __forceinline__ unsigned long long ffma2(unsigned long long a,
                                                    unsigned long long b,
                                                    unsigned long long c) {
    unsigned long long d;
    asm("fma.rn.f32x2 %0, %1, %2, %3;" : "=l"(d) : "l"(a), "l"(b), "l"(c));
    return d;
}
__device__ __forceinline__ float2 unpack2(unsigned long long v) {
    float2 f;
    asm("mov.b64 {%0,%1}, %2;" : "=f"(f.x), "=f"(f.y) : "l"(v));
    return f;
}

// ---------------- kernel: zero aggregation buffers ----------------
__global__ void k_zero() {
    float4 z = make_float4(0.f, 0.f, 0.f, 0.f);
    int n1 = NN * 2 * CC / 4;
    for (int i = blockIdx.x * blockDim.x + threadIdx.x; i < n1; i += gridDim.x * blockDim.x)
        reinterpret_cast<float4*>(g_agg_s)[i] = z;
    int n2 = NN * 6 * CC / 4;
    for (int i = blockIdx.x * blockDim.x + threadIdx.x; i < n2; i += gridDim.x * blockDim.x)
        reinterpret_cast<float4*>(g_agg_v)[i] = z;
}

// ---------------- kernel: node up-projection (fp16 outputs) ----------------
__global__ void __launch_bounds__(256) k_up(const float* __restrict__ scal,
                                            const float* __restrict__ nvec,
                                            const float* __restrict__ Wus,
                                            const float* __restrict__ Wuv) {
    extern __shared__ float sm[];
    float* sWs = sm;          // 64*64
    float* sWv = sm + 4096;   // 64*64
    float* sBuf = sm + 8192;  // 8 warps * 256
    int tid = threadIdx.x, wid = tid >> 5, l = tid & 31;
    for (int i = tid; i < 4096; i += 256) { sWs[i] = Wus[i]; sWv[i] = Wuv[i]; }
    __syncthreads();
    float* sc = sBuf + wid * 256;
    float* vb = sc + 64;
    int nwarp = gridDim.x * 8;
    for (int n = blockIdx.x * 8 + wid; n < NN; n += nwarp) {
        sc[l] = scal[n * 64 + l];
        sc[l + 32] = scal[n * 64 + l + 32];
#pragma unroll
        for (int q = 0; q < 6; q++) vb[l + q * 32] = nvec[n * 192 + l + q * 32];
        __syncwarp();
        float a0 = 0.f, a1 = 0.f;
#pragma unroll
        for (int k = 0; k < 64; k++) {
            float a = sc[k];
            a0 = fmaf(a, sWs[k * 64 + l], a0);
            a1 = fmaf(a, sWs[k * 64 + l + 32], a1);
        }
        g_s[n * 64 + l] = __float2half(a0);
        g_s[n * 64 + l + 32] = __float2half(a1);
        float v0[3] = {0.f, 0.f, 0.f}, v1[3] = {0.f, 0.f, 0.f};
#pragma unroll
        for (int k = 0; k < 64; k++) {
            float w0 = sWv[k * 64 + l], w1 = sWv[k * 64 + l + 32];
#pragma unroll
            for (int m = 0; m < 3; m++) {
                float a = vb[k * 3 + m];
                v0[m] = fmaf(a, w0, v0[m]);
                v1[m] = fmaf(a, w1, v1[m]);
            }
        }
#pragma unroll
        for (int m = 0; m < 3; m++) {
            g_v[n * 192 + l * 3 + m] = __float2half(v0[m]);
            g_v[n * 192 + (l + 32) * 3 + m] = __float2half(v1[m]);
        }
        __syncwarp();
    }
}

// ---------------- kernel: per-species skip projections ----------------
__global__ void __launch_bounds__(256) k_skip(const float* __restrict__ scal,
                                              const float* __restrict__ nvec,
                                              const int* __restrict__ specie,
                                              const float* __restrict__ Wss,
                                              const float* __restrict__ Wsv) {
    extern __shared__ float sm[];
    float* sS = sm;            // 32768
    float* sV = sm + 32768;    // 16384
    float* sBuf = sm + 49152;  // 8 * 256
    int tid = threadIdx.x, wid = tid >> 5, l = tid & 31;
    for (int i = tid; i < 32768; i += 256) sS[i] = Wss[i];
    for (int i = tid; i < 16384; i += 256) sV[i] = Wsv[i];
    __syncthreads();
    float* sc = sBuf + wid * 256;
    float* vb = sc + 64;
    int nwarp = gridDim.x * 8;
    for (int n = blockIdx.x * 8 + wid; n < NN; n += nwarp) {
        sc[l] = scal[n * 64 + l];
        sc[l + 32] = scal[n * 64 + l + 32];
#pragma unroll
        for (int q = 0; q < 6; q++) vb[l + q * 32] = nvec[n * 192 + l + q * 32];
        __syncwarp();
        int sp = specie[n];
        const float* ws = sS + sp * 8192;
        const float* wv = sV + sp * 4096;
        float a0 = 0.f, a1 = 0.f, a2 = 0.f, a3 = 0.f;
#pragma unroll
        for (int k = 0; k < 64; k++) {
            float x = sc[k];
            const float* w = ws + k * 128;
            a0 = fmaf(x, w[l], a0);
            a1 = fmaf(x, w[l + 32], a1);
            a2 = fmaf(x, w[l + 64], a2);
            a3 = fmaf(x, w[l + 96], a3);
        }
        g_skip_s[n * 128 + l] = a0;
        g_skip_s[n * 128 + l + 32] = a1;
        g_skip_s[n * 128 + l + 64] = a2;
        g_skip_s[n * 128 + l + 96] = a3;
        float v0[3] = {0.f, 0.f, 0.f}, v1[3] = {0.f, 0.f, 0.f};
#pragma unroll
        for (int k = 0; k < 64; k++) {
            float w0 = wv[k * 64 + l], w1 = wv[k * 64 + l + 32];
#pragma unroll
            for (int m = 0; m < 3; m++) {
                float a = vb[k * 3 + m];
                v0[m] = fmaf(a, w0, v0[m]);
                v1[m] = fmaf(a, w1, v1[m]);
            }
        }
#pragma unroll
        for (int m = 0; m < 3; m++) {
            g_skip_v[n * 192 + l * 3 + m] = v0[m];
            g_skip_v[n * 192 + (l + 32) * 3 + m] = v1[m];
        }
        __syncwarp();
    }
}

// ---------------- kernel: edge MLP -> g_mix (fp16), g_y (unchanged from R15) ----------------
__global__ void __launch_bounds__(256, 2) k_mlp(const float* __restrict__ vectors,
                                                const float* __restrict__ W0,
                                                const float* __restrict__ W1,
                                                const float* __restrict__ W2) {
    extern __shared__ float sm[];
    float* sW0 = sm;                 // 512
    float* sW1 = sm + 512;           // 4096
    float* sW2 = sm + 4608;          // 16384
    float* sH  = sm + 20992;         // 64*65 = 4160, reused H0->H1
    float* sF  = sm + 25152;         // 64*9  = 576  -> total 25728 floats

    int tid = threadIdx.x;
    for (int i = tid; i < 512; i += 256) sW0[i] = W0[i];
    for (int i = tid; i < 4096; i += 256) sW1[i] = W1[i];
    for (int i = tid; i < 16384; i += 256) sW2[i] = W2[i];
    __syncthreads();

    const int og = tid >> 3;  // 0..31
    const int eg = tid & 7;   // 0..7
    const float SQRT2 = 1.41421356237309515f;
    const float SQRT3 = 1.73205080756887729f;
    const float PI = 3.14159265358979323846f;

    int ntile = EE / 64;
    for (int t = blockIdx.x; t < ntile; t += gridDim.x) {
        int e0 = t * 64;
        // ---- phase 1: per-edge features (threads 0..63) ----
        if (tid < 64) {
            int e = e0 + tid;
            float vx = vectors[e * 3 + 0];
            float vy = vectors[e * 3 + 1];
            float vz = vectors[e * 3 + 2];
            float x = sqrtf(vx * vx + vy * vy + vz * vz);
            float sx = (x == 0.f) ? 1.f : x;
            float inv = 1.f / sx;
            float4 yv = make_float4(SQRT3 * vx * inv, SQRT3 * vy * inv, SQRT3 * vz * inv, 0.f);
            *reinterpret_cast<float4*>(g_y + e * 4) = yv;
            float u = fminf(x, 1.f);
            float u2 = u * u, u3 = u2 * u, u6 = u3 * u3, u7 = u6 * u, u8 = u7 * u;
            float env = (x < 1.f) ? (1.f - 28.f * u6 + 48.f * u7 - 21.f * u8) : 0.f;
            float s1, c1;
            sincosf(PI * x, &s1, &c1);
            float pref = SQRT2 * inv * env;
            float sn = s1, cn = c1;
            sF[tid * 9 + 0] = pref * sn;
#pragma unroll
            for (int b = 1; b < 8; b++) {
                float sn1 = sn * c1 + cn * s1;
                float cn1 = cn * c1 - sn * s1;
                sn = sn1; cn = cn1;
                sF[tid * 9 + b] = pref * sn;
            }
        }
        __syncthreads();

        // ---- phase 2: h0 = swish(feat @ W0) ----
        {
            float a0[8], a1[8];
#pragma unroll
            for (int i = 0; i < 8; i++) { a0[i] = 0.f; a1[i] = 0.f; }
#pragma unroll
            for (int b = 0; b < 8; b++) {
                float w0 = sW0[b * 64 + og];
                float w1 = sW0[b * 64 + og + 32];
#pragma unroll
                for (int i = 0; i < 8; i++) {
                    float f = sF[(eg + 8 * i) * 9 + b];
                    a0[i] = fmaf(f, w0, a0[i]);
                    a1[i] = fmaf(f, w1, a1[i]);
                }
            }
#pragma unroll
            for (int i = 0; i < 8; i++) {
                sH[(eg + 8 * i) * 65 + og] = swishf(a0[i]);
                sH[(eg + 8 * i) * 65 + og + 32] = swishf(a1[i]);
            }
        }
        __syncthreads();

        // ---- phase 3: h1 = swish(h0 @ W1), FFMA2 over output pair (2og, 2og+1) ----
        {
            unsigned long long acc[8];
#pragma unroll
            for (int i = 0; i < 8; i++) acc[i] = 0ULL;
            const unsigned long long* w1p =
                reinterpret_cast<const unsigned long long*>(sW1 + 2 * og);
#pragma unroll 2
            for (int k = 0; k < 64; k++) {
                unsigned long long wp = w1p[k * 32];
#pragma unroll
                for (int i = 0; i < 8; i++) {
                    unsigned long long ad = dup2(sH[(eg + 8 * i) * 65 + k]);
                    acc[i] = ffma2(ad, wp, acc[i]);
                }
            }
            __syncthreads();
#pragma unroll
            for (int i = 0; i < 8; i++) {
                float2 f = unpack2(acc[i]);
                sH[(eg + 8 * i) * 65 + 2 * og] = swishf(f.x);
                sH[(eg + 8 * i) * 65 + 2 * og + 1] = swishf(f.y);
            }
        }
        __syncthreads();

        // ---- phase 4: mix = h1 @ W2, FFMA2, thread tile 8e x 4 j-pairs ----
        unsigned long long acc[8][4];
#pragma unroll
        for (int i = 0; i < 8; i++)
#pragma unroll
            for (int q = 0; q < 4; q++) acc[i][q] = 0ULL;
        {
            const int j0 = og * 8;
#pragma unroll 2
            for (int k = 0; k < 64; k++) {
                ulonglong2 b0 = *reinterpret_cast<const ulonglong2*>(sW2 + k * 256 + j0);
                ulonglong2 b1 = *reinterpret_cast<const ulonglong2*>(sW2 + k * 256 + j0 + 4);
#pragma unroll
                for (int i = 0; i < 8; i++) {
                    unsigned long long ad = dup2(sH[(eg + 8 * i) * 65 + k]);
                    acc[i][0] = ffma2(ad, b0.x, acc[i][0]);
                    acc[i][1] = ffma2(ad, b0.y, acc[i][1]);
                    acc[i][2] = ffma2(ad, b1.x, acc[i][2]);
                    acc[i][3] = ffma2(ad, b1.y, acc[i][3]);
                }
            }
        }

        // ---- phase 5': convert to fp16, store 16B packets (8 halves) ----
        {
            const int j0 = og * 8;
#pragma unroll
            for (int i = 0; i < 8; i++) {
                int e = e0 + eg + 8 * i;
                union { uint4 u; __half2 h[4]; } pk;
                pk.h[0] = __float22half2_rn(unpack2(acc[i][0]));
                pk.h[1] = __float22half2_rn(unpack2(acc[i][1]));
                pk.h[2] = __float22half2_rn(unpack2(acc[i][2]));
                pk.h[3] = __float22half2_rn(unpack2(acc[i][3]));
                *reinterpret_cast<uint4*>(g_mix + e * 256 + j0) = pk.u;
            }
        }
        __syncthreads();
    }
}

// ---------------- kernel: gather + message + scatter (warp-per-edge, all-fp16 loads) ----------------
__global__ void __launch_bounds__(256) k_scatter(const int* __restrict__ senders,
                                                 const int* __restrict__ receivers) {
    __shared__ float sb[8][520];  // per warp: S[64] V[192] M[256] Y[4] (+pad)
    int tid = threadIdx.x;
    int w = tid >> 5, l = tid & 31;
    const float INV_SQRT3 = 0.57735026918962576f;
    float* S = sb[w];
    float* V = S + 64;
    float* M = V + 192;
    float* Yp = M + 256;
    int nwarp = gridDim.x * 8;
    for (int e = blockIdx.x * 8 + w; e < EE; e += nwarp) {
        int snd = senders[e];
        int rcv = receivers[e];
        // mix fp16: 256 halves; lane l stages floats [4l..4l+3] and [128+4l..]
#pragma unroll
        for (int half = 0; half < 2; half++) {
            int base = half * 128 + l * 4;
            union { uint2 u; __half2 h[2]; } pk;
            pk.u = *reinterpret_cast<const uint2*>(g_mix + e * 256 + base);
            float2 f0 = __half22float2(pk.h[0]);
            float2 f1 = __half22float2(pk.h[1]);
            *reinterpret_cast<float4*>(M + base) = make_float4(f0.x, f0.y, f1.x, f1.y);
        }
        // v fp16: 192 halves; lane l loads halves [4l..4l+3]; lanes<16 also [128+4l..]
        {
            union { uint2 u; __half2 h[2]; } pk;
            pk.u = *reinterpret_cast<const uint2*>(g_v + snd * 192 + l * 4);
            float2 f0 = __half22float2(pk.h[0]);
            float2 f1 = __half22float2(pk.h[1]);
            *reinterpret_cast<float4*>(V + l * 4) = make_float4(f0.x, f0.y, f1.x, f1.y);
            if (l < 16) {
                pk.u = *reinterpret_cast<const uint2*>(g_v + snd * 192 + 128 + l * 4);
                f0 = __half22float2(pk.h[0]);
                f1 = __half22float2(pk.h[1]);
                *reinterpret_cast<float4*>(V + 128 + l * 4) = make_float4(f0.x, f0.y, f1.x, f1.y);
            }
        }
        // s fp16: 64 halves; lanes<16 load 4 halves each
        if (l < 16) {
            union { uint2 u; __half2 h[2]; } pk;
            pk.u = *reinterpret_cast<const uint2*>(g_s + snd * 64 + l * 4);
            float2 f0 = __half22float2(pk.h[0]);
            float2 f1 = __half22float2(pk.h[1]);
            *reinterpret_cast<float4*>(S + l * 4) = make_float4(f0.x, f0.y, f1.x, f1.y);
        }
        if (l == 0)
            *reinterpret_cast<float4*>(Yp) = *reinterpret_cast<const float4*>(g_y + e * 4);
        __syncwarp();

#pragma unroll
        for (int j = 0; j < 4; j++) {
            int o = l + 32 * j;  // 0..127
            if (o < 16) {
                int c = o * 4;
                red4(g_agg_s + rcv * 128 + c,
                     S[c] * M[c], S[c + 1] * M[c + 1],
                     S[c + 2] * M[c + 2], S[c + 3] * M[c + 3]);
            } else if (o < 32) {
                int c = (o - 16) * 4;
                float y0 = Yp[0], y1 = Yp[1], y2 = Yp[2];
                float v[4];
#pragma unroll
                for (int t = 0; t < 4; t++) {
                    int cc = c + t;
                    v[t] = (V[cc * 3] * y0 + V[cc * 3 + 1] * y1 + V[cc * 3 + 2] * y2)
                           * INV_SQRT3 * M[64 + cc];
                }
                red4(g_agg_s + rcv * 128 + 64 + c, v[0], v[1], v[2], v[3]);
            } else {
                int q = o - 32;          // 0..95
                int m = q >> 5, cb = q & 31;
                int c2 = cb * 4;
                float v[4];
                if (c2 < 64) {
#pragma unroll
                    for (int t = 0; t < 4; t++)
                        v[t] = V[(c2 + t) * 3 + m] * M[128 + c2 + t];
                } else {
                    int c = c2 - 64;
                    float ym = Yp[m];
#pragma unroll
                    for (int t = 0; t < 4; t++)
                        v[t] = S[c + t] * ym * M[192 + c + t];
                }
                red4(g_agg_v + rcv * 384 + m * 128 + c2, v[0], v[1], v[2], v[3]);
            }
        }
        __syncwarp();
    }
}

// ---------------- kernel: final down-projection + skip + gating + output ----------------
__global__ void __launch_bounds__(256) k_final(const float* __restrict__ Wds,
                                               const float* __restrict__ Wdv,
                                               float* __restrict__ out) {
    extern __shared__ float sm[];
    float* sWs = sm;            // 16384
    float* sWv = sm + 16384;    // 8192
    float* sBuf = sm + 24576;   // 8 * 520
    int tid = threadIdx.x, wid = tid >> 5, l = tid & 31;
    for (int i = tid; i < 16384; i += 256) sWs[i] = Wds[i];
    for (int i = tid; i < 8192; i += 256) sWv[i] = Wdv[i];
    __syncthreads();
    float* As = sBuf + wid * 520;
    float* Av = As + 128;
    const float INV = 0.25f;
    int nwarp = gridDim.x * 8;
    for (int n = blockIdx.x * 8 + wid; n < NN; n += nwarp) {
#pragma unroll
        for (int q = 0; q < 4; q++) As[l + 32 * q] = g_agg_s[n * 128 + l + 32 * q];
#pragma unroll
        for (int q = 0; q < 12; q++) Av[l + 32 * q] = g_agg_v[n * 384 + l + 32 * q];
        __syncwarp();
        float a0 = 0.f, a1 = 0.f, a2 = 0.f, a3 = 0.f;
#pragma unroll 4
        for (int k = 0; k < 128; k++) {
            float x = As[k];
            const float* w = sWs + k * 128;
            a0 = fmaf(x, w[l], a0);
            a1 = fmaf(x, w[l + 32], a1);
            a2 = fmaf(x, w[l + 64], a2);
            a3 = fmaf(x, w[l + 96], a3);
        }
        float os0 = INV * a0 + g_skip_s[n * 128 + l];
        float os1 = INV * a1 + g_skip_s[n * 128 + l + 32];
        float os2 = INV * a2 + g_skip_s[n * 128 + l + 64];
        float os3 = INV * a3 + g_skip_s[n * 128 + l + 96];
        float scal0 = swishf(os0), scal1 = swishf(os1);
        float gate0 = swishf(os2), gate1 = swishf(os3);
        float v0[3] = {0.f, 0.f, 0.f}, v1[3] = {0.f, 0.f, 0.f};
#pragma unroll 4
        for (int k = 0; k < 128; k++) {
            float w0 = sWv[k * 64 + l], w1 = sWv[k * 64 + l + 32];
#pragma unroll
            for (int m = 0; m < 3; m++) {
                float a = Av[m * 128 + k];
                v0[m] = fmaf(a, w0, v0[m]);
                v1[m] = fmaf(a, w1, v1[m]);
            }
        }
        out[n * 256 + l] = scal0;
        out[n * 256 + l + 32] = scal1;
#pragma unroll
        for (int m = 0; m < 3; m++) {
            float ov0 = INV * v0[m] + g_skip_v[n * 192 + l * 3 + m];
            float ov1 = INV * v1[m] + g_skip_v[n * 192 + (l + 32) * 3 + m];
            out[n * 256 + 64 + l * 3 + m] = ov0 * gate0;
            out[n * 256 + 64 + (l + 32) * 3 + m] = ov1 * gate1;
        }
        __syncwarp();
    }
}

// ---------------- launch (R13/R15 configuration) ----------------
extern "C" void kernel_launch(void* const* d_in, const int* in_sizes, int n_in,
                              void* d_out, int out_size) {
    const float* vectors      = (const float*)d_in[0];
    const float* node_scalars = (const float*)d_in[1];
    const float* node_vectors = (const float*)d_in[2];
    const int*   node_specie  = (const int*)d_in[3];
    const int*   senders      = (const int*)d_in[4];
    const int*   receivers    = (const int*)d_in[5];
    const float* W_skip_s     = (const float*)d_in[6];
    const float* W_skip_v     = (const float*)d_in[7];
    const float* W_up_s       = (const float*)d_in[8];
    const float* W_up_v       = (const float*)d_in[9];
    const float* W_mlp0       = (const float*)d_in[10];
    const float* W_mlp1       = (const float*)d_in[11];
    const float* W_mlp2       = (const float*)d_in[12];
    const float* W_down_s     = (const float*)d_in[13];
    const float* W_down_v     = (const float*)d_in[14];
    float* out = (float*)d_out;

    const int UP_SMEM    = (8192 + 8 * 256) * 4;            // 40 KB
    const int SKIP_SMEM  = (49152 + 8 * 256) * 4;           // 200 KB
    const int MLP_SMEM   = 25728 * 4;                       // ~100.5 KB -> 2 blocks/SM
    const int FINAL_SMEM = (24576 + 8 * 520) * 4;           // ~114.5 KB

    cudaFuncSetAttribute(k_skip,  cudaFuncAttributeMaxDynamicSharedMemorySize, SKIP_SMEM);
    cudaFuncSetAttribute(k_mlp,   cudaFuncAttributeMaxDynamicSharedMemorySize, MLP_SMEM);
    cudaFuncSetAttribute(k_final, cudaFuncAttributeMaxDynamicSharedMemorySize, FINAL_SMEM);

    k_zero<<<2048, 256>>>();
    k_up<<<512, 256, UP_SMEM>>>(node_scalars, node_vectors, W_up_s, W_up_v);
    k_skip<<<296, 256, SKIP_SMEM>>>(node_scalars, node_vectors, node_specie, W_skip_s, W_skip_v);
    k_mlp<<<296, 256, MLP_SMEM>>>(vectors, W_mlp0, W_mlp1, W_mlp2);
    k_scatter<<<2960, 256>>>(senders, receivers);
    k_final<<<296, 256, FINAL_SMEM>>>(W_down_s, W_down_v, out);
}